// round 4
// baseline (speedup 1.0000x reference)
#include <cuda_runtime.h>
#include <cuda_bf16.h>

// GCN link predictor:
//   h1 = x @ W1;  a1 = relu( scatter(h1*norm) + h1*dinv^2 + b1 )
//   h2 = a1 @ W2; a2 =       scatter(h2*norm) + h2*dinv^2 + b2
//   logits[e] = dot(a2[src[e]], a2[dst[e]])
//
// edge_index may be int32 (JAX default, x64 disabled) or int64 — auto-detected
// on device and converted once into packed int32 arrays.
//
// NOTE: __device__ scratch arrays are ONLY referenced inside device code.
// Passing them as host-side kernel arguments is UB (host shadow symbol), and
// on GB300 (ATS) it silently reads/writes host memory instead of faulting.

#define N_NODES 100000
#define MAX_E   1600000
#define D_IN    32
#define D_HID   64
#define D_OUT   32

// Static scratch (allocation-free rule). 16B-aligned for float4 / red.v4.
__device__ __align__(16) float g_deg [N_NODES];
__device__ __align__(16) float g_dinv[N_NODES];
__device__ __align__(16) float g_h1  [N_NODES * D_HID];
__device__ __align__(16) float g_a1  [N_NODES * D_HID];
__device__ __align__(16) float g_h2  [N_NODES * D_OUT];
__device__ __align__(16) float g_a2  [N_NODES * D_OUT];
__device__ __align__(16) float g_norm[MAX_E];
__device__ __align__(16) int   g_src [MAX_E];
__device__ __align__(16) int   g_dst [MAX_E];
__device__ int g_is64;

// ---------------------------------------------------------------------------
// 0) dtype detect + index conversion (int64 vs int32 edge_index)
// ---------------------------------------------------------------------------
__global__ void k_detect(const void* __restrict__ ei) {
    if (threadIdx.x == 0 && blockIdx.x == 0) {
        const long long* p = (const long long*)ei;
        int is64 = 1;
        #pragma unroll
        for (int i = 0; i < 8; i++) {
            long long v = p[i];
            if (v < 0 || v >= N_NODES) is64 = 0;
        }
        g_is64 = is64;
    }
}

__global__ void k_convert(const void* __restrict__ ei, int E) {
    int i = blockIdx.x * blockDim.x + threadIdx.x;
    if (i >= 2 * E) return;
    int v;
    if (g_is64) v = (int)((const long long*)ei)[i];
    else        v = ((const int*)ei)[i];
    // clamp: insurance against mis-detection (shows as rel_err, not crash)
    v = min(max(v, 0), N_NODES - 1);
    if (i < E) g_src[i] = v;
    else       g_dst[i - E] = v;
}

// ---------------------------------------------------------------------------
// 1) degree init + accumulate + rsqrt + per-edge norm
// ---------------------------------------------------------------------------
__global__ void k_deg_init(int n) {
    int i = blockIdx.x * blockDim.x + threadIdx.x;
    if (i < n) g_deg[i] = 1.0f;  // implicit self-loop
}

__global__ void k_deg_accum(int E) {
    int e = blockIdx.x * blockDim.x + threadIdx.x;
    if (e < E) atomicAdd(&g_deg[g_dst[e]], 1.0f);
}

__global__ void k_dinv(int n) {
    int i = blockIdx.x * blockDim.x + threadIdx.x;
    if (i < n) g_dinv[i] = rsqrtf(g_deg[i]);
}

__global__ void k_norm(int E) {
    int e = blockIdx.x * blockDim.x + threadIdx.x;
    if (e < E) g_norm[e] = g_dinv[g_src[e]] * g_dinv[g_dst[e]];
}

// ---------------------------------------------------------------------------
// 2) GEMM1: h1 = x @ W1 ; a1 = h1 * dinv^2 (self-loop init of aggregator)
// ---------------------------------------------------------------------------
__global__ void k_gemm1(const float* __restrict__ x, const float* __restrict__ W1, int n) {
    __shared__ float sW[D_IN * D_HID];   // 8 KB
    __shared__ float sx[4 * D_IN];       // 512 B
    int tid = threadIdx.x;
    for (int i = tid; i < D_IN * D_HID; i += 256) sW[i] = W1[i];
    int node0 = blockIdx.x * 4;
    if (tid < 4 * D_IN) {
        int nn = node0 + tid / D_IN;
        sx[tid] = (nn < n) ? x[nn * D_IN + (tid % D_IN)] : 0.0f;
    }
    __syncthreads();
    int local = tid >> 6;          // 0..3
    int j     = tid & 63;          // 0..63
    int node  = node0 + local;
    if (node < n) {
        float acc = 0.0f;
        #pragma unroll
        for (int k = 0; k < D_IN; k++)
            acc = fmaf(sx[local * D_IN + k], sW[k * D_HID + j], acc);
        float di = g_dinv[node];
        g_h1[node * D_HID + j] = acc;
        g_a1[node * D_HID + j] = acc * di * di;
    }
}

// ---------------------------------------------------------------------------
// 3) edge scatter: agg[dst] += h[src] * norm, vector REDG (16B atomic add)
//    One thread per (edge, 4-float chunk). Buffers resolved IN DEVICE CODE.
// ---------------------------------------------------------------------------
template <int LAYER>
__global__ void k_scatter(int E) {
    constexpr int D = (LAYER == 1) ? D_HID : D_OUT;
    constexpr int Q = D / 4;
    const float* __restrict__ h   = (LAYER == 1) ? g_h1 : g_h2;
    float*       __restrict__ agg = (LAYER == 1) ? g_a1 : g_a2;
    int idx = blockIdx.x * blockDim.x + threadIdx.x;
    int e = idx / Q;
    int q = idx % Q;
    if (e >= E) return;
    int s = g_src[e];
    int d = g_dst[e];
    float norm = g_norm[e];
    float4 v = *reinterpret_cast<const float4*>(h + s * D + q * 4);
    float* p = agg + d * D + q * 4;
    asm volatile("red.global.add.v4.f32 [%0], {%1, %2, %3, %4};"
                 :: "l"(p), "f"(v.x * norm), "f"(v.y * norm),
                    "f"(v.z * norm), "f"(v.w * norm)
                 : "memory");
}

// ---------------------------------------------------------------------------
// 4) finalize layer 1: a1 = relu(a1 + b1), float4 vectorized
// ---------------------------------------------------------------------------
__global__ void k_final1(const float* __restrict__ b1, int total4) {
    int i = blockIdx.x * blockDim.x + threadIdx.x;
    if (i >= total4) return;
    int base = (i * 4) & (D_HID - 1);
    float4 v = *reinterpret_cast<float4*>(g_a1 + i * 4);
    v.x = fmaxf(v.x + b1[base + 0], 0.0f);
    v.y = fmaxf(v.y + b1[base + 1], 0.0f);
    v.z = fmaxf(v.z + b1[base + 2], 0.0f);
    v.w = fmaxf(v.w + b1[base + 3], 0.0f);
    *reinterpret_cast<float4*>(g_a1 + i * 4) = v;
}

// ---------------------------------------------------------------------------
// 5) GEMM2: h2 = a1 @ W2 ; a2 = h2 * dinv^2
// ---------------------------------------------------------------------------
__global__ void k_gemm2(const float* __restrict__ W2, int n) {
    __shared__ float sW[D_HID * D_OUT];  // 8 KB
    __shared__ float sx[8 * D_HID];      // 2 KB
    int tid = threadIdx.x;
    for (int i = tid; i < D_HID * D_OUT; i += 256) sW[i] = W2[i];
    int node0 = blockIdx.x * 8;
    for (int i = tid; i < 8 * D_HID; i += 256) {
        int nn = node0 + i / D_HID;
        sx[i] = (nn < n) ? g_a1[nn * D_HID + (i % D_HID)] : 0.0f;
    }
    __syncthreads();
    int local = tid >> 5;          // 0..7
    int j     = tid & 31;          // 0..31
    int node  = node0 + local;
    if (node < n) {
        float acc = 0.0f;
        #pragma unroll
        for (int k = 0; k < D_HID; k++)
            acc = fmaf(sx[local * D_HID + k], sW[k * D_OUT + j], acc);
        float di = g_dinv[node];
        g_h2[node * D_OUT + j] = acc;
        g_a2[node * D_OUT + j] = acc * di * di;
    }
}

// ---------------------------------------------------------------------------
// 6) finalize layer 2: a2 += b2 (no relu), float4 vectorized
// ---------------------------------------------------------------------------
__global__ void k_final2(const float* __restrict__ b2, int total4) {
    int i = blockIdx.x * blockDim.x + threadIdx.x;
    if (i >= total4) return;
    int base = (i * 4) & (D_OUT - 1);
    float4 v = *reinterpret_cast<float4*>(g_a2 + i * 4);
    v.x += b2[base + 0];
    v.y += b2[base + 1];
    v.z += b2[base + 2];
    v.w += b2[base + 3];
    *reinterpret_cast<float4*>(g_a2 + i * 4) = v;
}

// ---------------------------------------------------------------------------
// 7) per-edge logits: 8 threads/edge, float4 loads + shuffle reduce
// ---------------------------------------------------------------------------
__global__ void k_logits(float* __restrict__ out, int E) {
    int idx = blockIdx.x * blockDim.x + threadIdx.x;
    int e = idx >> 3;
    int q = idx & 7;
    if (e >= E) return;
    int s = g_src[e];
    int d = g_dst[e];
    float4 vs = *reinterpret_cast<const float4*>(g_a2 + s * D_OUT + q * 4);
    float4 vd = *reinterpret_cast<const float4*>(g_a2 + d * D_OUT + q * 4);
    float p = vs.x * vd.x + vs.y * vd.y + vs.z * vd.z + vs.w * vd.w;
    p += __shfl_xor_sync(0xffffffffu, p, 1);
    p += __shfl_xor_sync(0xffffffffu, p, 2);
    p += __shfl_xor_sync(0xffffffffu, p, 4);
    if (q == 0) out[e] = p;
}

// ---------------------------------------------------------------------------
extern "C" void kernel_launch(void* const* d_in, const int* in_sizes, int n_in,
                              void* d_out, int out_size) {
    const float* x   = (const float*)d_in[0];
    const void*  ei  = d_in[1];
    const float* W1  = (const float*)d_in[2];
    const float* b1  = (const float*)d_in[3];
    const float* W2  = (const float*)d_in[4];
    const float* b2  = (const float*)d_in[5];
    float*       out = (float*)d_out;

    const int N = in_sizes[0] / D_IN;       // 100000
    const int E = in_sizes[1] / 2;          // 1600000
    const int T = 256;

    // index conversion
    k_detect<<<1, 32>>>(ei);
    k_convert<<<(2 * E + T - 1) / T, T>>>(ei, E);

    // degree / dinv / norm
    k_deg_init<<<(N + T - 1) / T, T>>>(N);
    k_deg_accum<<<(E + T - 1) / T, T>>>(E);
    k_dinv<<<(N + T - 1) / T, T>>>(N);
    k_norm<<<(E + T - 1) / T, T>>>(E);

    // layer 1
    k_gemm1<<<(N + 3) / 4, T>>>(x, W1, N);
    {
        long long total = (long long)E * (D_HID / 4);
        k_scatter<1><<<(int)((total + T - 1) / T), T>>>(E);
    }
    k_final1<<<(N * D_HID / 4 + T - 1) / T, T>>>(b1, N * D_HID / 4);

    // layer 2
    k_gemm2<<<(N + 7) / 8, T>>>(W2, N);
    {
        long long total = (long long)E * (D_OUT / 4);
        k_scatter<2><<<(int)((total + T - 1) / T), T>>>(E);
    }
    k_final2<<<(N * D_OUT / 4 + T - 1) / T, T>>>(b2, N * D_OUT / 4);

    // edge logits
    {
        long long total = (long long)E * 8;
        k_logits<<<(int)((total + T - 1) / T), T>>>(out, E);
    }
}

// round 5
// speedup vs baseline: 1.1181x; 1.1181x over previous
#include <cuda_runtime.h>
#include <cuda_bf16.h>

// GCN link predictor, CSR gather formulation:
//   deg/dinv from dst histogram (+1 self loop)
//   CSR: edges grouped by dst, payload = (src, norm=dinv[src]*dinv[dst])
//   h1 = x @ W1;  a1 = relu( gather_sum(h1[src]*norm) + h1*dinv^2 + b1 )
//   h2 = a1 @ W2; a2 =       gather_sum(h2[src]*norm) + h2*dinv^2 + b2
//   logits[e] = dot(a2[src[e]], a2[dst[e]])
//
// NOTE: __device__ scratch arrays are ONLY referenced inside device code
// (host-side use of the symbol is UB and silently corrupts via ATS on GB300).

#define N_NODES 100000
#define MAX_E   1600000
#define D_IN    32
#define D_HID   64
#define D_OUT   32

#define NCHUNK  2048   // scan chunks
// ceil(N_NODES / NCHUNK)
#define CHUNK   ((N_NODES + NCHUNK - 1) / NCHUNK)

__device__ __align__(16) int   g_cnt [N_NODES];     // in-degree (no self loop)
__device__ __align__(16) int   g_off [N_NODES];     // CSR row start
__device__ __align__(16) int   g_cur [N_NODES];     // fill cursor
__device__ __align__(16) float g_dinv[N_NODES];
__device__ __align__(16) float g_h1  [N_NODES * D_HID];
__device__ __align__(16) float g_a1  [N_NODES * D_HID];
__device__ __align__(16) float g_h2  [N_NODES * D_OUT];
__device__ __align__(16) float g_a2  [N_NODES * D_OUT];
__device__ __align__(16) int   g_src [MAX_E];
__device__ __align__(16) int   g_dst [MAX_E];
__device__ __align__(16) int   g_csr_src [MAX_E];
__device__ __align__(16) float g_csr_norm[MAX_E];
__device__ __align__(16) int   g_part[NCHUNK];
__device__ int g_is64;

// ---------------------------------------------------------------------------
// 0) dtype detect + index conversion (int64 vs int32 edge_index)
// ---------------------------------------------------------------------------
__global__ void k_detect(const void* __restrict__ ei) {
    if (threadIdx.x == 0 && blockIdx.x == 0) {
        const long long* p = (const long long*)ei;
        int is64 = 1;
        #pragma unroll
        for (int i = 0; i < 8; i++) {
            long long v = p[i];
            if (v < 0 || v >= N_NODES) is64 = 0;
        }
        g_is64 = is64;
    }
}

__global__ void k_convert(const void* __restrict__ ei, int E) {
    int i = blockIdx.x * blockDim.x + threadIdx.x;
    if (i >= 2 * E) return;
    int v;
    if (g_is64) v = (int)((const long long*)ei)[i];
    else        v = ((const int*)ei)[i];
    v = min(max(v, 0), N_NODES - 1);
    if (i < E) g_src[i] = v;
    else       g_dst[i - E] = v;
}

// ---------------------------------------------------------------------------
// 1) degree histogram + dinv
// ---------------------------------------------------------------------------
__global__ void k_cnt_init(int n) {
    int i = blockIdx.x * blockDim.x + threadIdx.x;
    if (i < n) g_cnt[i] = 0;
}

__global__ void k_deg_accum(int E) {
    int e = blockIdx.x * blockDim.x + threadIdx.x;
    if (e < E) atomicAdd(&g_cnt[g_dst[e]], 1);
}

__global__ void k_dinv(int n) {
    int i = blockIdx.x * blockDim.x + threadIdx.x;
    if (i < n) g_dinv[i] = rsqrtf((float)(g_cnt[i] + 1));  // +1 self loop
}

// ---------------------------------------------------------------------------
// 2) exclusive scan of g_cnt -> g_off (2-level, NCHUNK chunks)
// ---------------------------------------------------------------------------
__global__ void k_scan_a(int n) {   // grid*block == NCHUNK
    int c = blockIdx.x * blockDim.x + threadIdx.x;
    if (c >= NCHUNK) return;
    int beg = c * CHUNK, end = min(beg + CHUNK, n);
    int s = 0;
    for (int i = beg; i < end; i++) s += g_cnt[i];
    g_part[c] = s;
}

__global__ void k_scan_b() {        // 1 block, 256 threads; 8 parts/thread
    __shared__ int sh[256];
    int t = threadIdx.x;
    int base = t * 8;
    int loc[8]; int sum = 0;
    #pragma unroll
    for (int i = 0; i < 8; i++) { loc[i] = g_part[base + i]; sum += loc[i]; }
    sh[t] = sum;
    __syncthreads();
    // Hillis-Steele inclusive scan of sh[256]
    #pragma unroll
    for (int d = 1; d < 256; d <<= 1) {
        int v = (t >= d) ? sh[t - d] : 0;
        __syncthreads();
        sh[t] += v;
        __syncthreads();
    }
    int run = (t == 0) ? 0 : sh[t - 1];   // exclusive base for this thread
    #pragma unroll
    for (int i = 0; i < 8; i++) { int tmp = loc[i]; g_part[base + i] = run; run += tmp; }
}

__global__ void k_scan_c(int n) {   // grid*block == NCHUNK
    int c = blockIdx.x * blockDim.x + threadIdx.x;
    if (c >= NCHUNK) return;
    int beg = c * CHUNK, end = min(beg + CHUNK, n);
    int run = g_part[c];
    for (int i = beg; i < end; i++) {
        g_off[i] = run;
        g_cur[i] = run;
        run += g_cnt[i];
    }
}

// ---------------------------------------------------------------------------
// 3) CSR fill: group edges by dst, payload (src, norm)
// ---------------------------------------------------------------------------
__global__ void k_csr_fill(int E) {
    int e = blockIdx.x * blockDim.x + threadIdx.x;
    if (e >= E) return;
    int s = g_src[e];
    int d = g_dst[e];
    int pos = atomicAdd(&g_cur[d], 1);
    g_csr_src[pos]  = s;
    g_csr_norm[pos] = g_dinv[s] * g_dinv[d];
}

// ---------------------------------------------------------------------------
// 4) GEMM1: h1 = x @ W1
// ---------------------------------------------------------------------------
__global__ void k_gemm1(const float* __restrict__ x, const float* __restrict__ W1, int n) {
    __shared__ float sW[D_IN * D_HID];   // 8 KB
    __shared__ float sx[4 * D_IN];
    int tid = threadIdx.x;
    for (int i = tid; i < D_IN * D_HID; i += 256) sW[i] = W1[i];
    int node0 = blockIdx.x * 4;
    if (tid < 4 * D_IN) {
        int nn = node0 + tid / D_IN;
        sx[tid] = (nn < n) ? x[nn * D_IN + (tid % D_IN)] : 0.0f;
    }
    __syncthreads();
    int local = tid >> 6;
    int j     = tid & 63;
    int node  = node0 + local;
    if (node < n) {
        float acc = 0.0f;
        #pragma unroll
        for (int k = 0; k < D_IN; k++)
            acc = fmaf(sx[local * D_IN + k], sW[k * D_HID + j], acc);
        g_h1[node * D_HID + j] = acc;
    }
}

// ---------------------------------------------------------------------------
// 5) gather layer 1: a1 = relu( sum h1[src]*norm + h1*dinv^2 + b1 )
//    16 threads per node (float4 over 64 cols), 16 nodes per block.
// ---------------------------------------------------------------------------
__global__ void k_gather1(const float* __restrict__ b1, int n) {
    int t    = threadIdx.x & 15;
    int grp  = threadIdx.x >> 4;
    int node = blockIdx.x * 16 + grp;
    if (node >= n) return;
    int beg = g_off[node];
    int end = beg + g_cnt[node];
    float4 acc = make_float4(0.f, 0.f, 0.f, 0.f);
    for (int i = beg; i < end; i++) {
        int   s = __ldg(&g_csr_src[i]);
        float w = __ldg(&g_csr_norm[i]);
        float4 v = *reinterpret_cast<const float4*>(g_h1 + s * D_HID + t * 4);
        acc.x = fmaf(v.x, w, acc.x);
        acc.y = fmaf(v.y, w, acc.y);
        acc.z = fmaf(v.z, w, acc.z);
        acc.w = fmaf(v.w, w, acc.w);
    }
    float di = g_dinv[node];
    float d2 = di * di;
    float4 self = *reinterpret_cast<const float4*>(g_h1 + node * D_HID + t * 4);
    float4 bb   = *reinterpret_cast<const float4*>(b1 + t * 4);
    acc.x = fmaxf(fmaf(self.x, d2, acc.x) + bb.x, 0.f);
    acc.y = fmaxf(fmaf(self.y, d2, acc.y) + bb.y, 0.f);
    acc.z = fmaxf(fmaf(self.z, d2, acc.z) + bb.z, 0.f);
    acc.w = fmaxf(fmaf(self.w, d2, acc.w) + bb.w, 0.f);
    *reinterpret_cast<float4*>(g_a1 + node * D_HID + t * 4) = acc;
}

// ---------------------------------------------------------------------------
// 6) GEMM2: h2 = a1 @ W2
// ---------------------------------------------------------------------------
__global__ void k_gemm2(const float* __restrict__ W2, int n) {
    __shared__ float sW[D_HID * D_OUT];  // 8 KB
    __shared__ float sx[8 * D_HID];
    int tid = threadIdx.x;
    for (int i = tid; i < D_HID * D_OUT; i += 256) sW[i] = W2[i];
    int node0 = blockIdx.x * 8;
    for (int i = tid; i < 8 * D_HID; i += 256) {
        int nn = node0 + i / D_HID;
        sx[i] = (nn < n) ? g_a1[nn * D_HID + (i % D_HID)] : 0.0f;
    }
    __syncthreads();
    int local = tid >> 5;
    int j     = tid & 31;
    int node  = node0 + local;
    if (node < n) {
        float acc = 0.0f;
        #pragma unroll
        for (int k = 0; k < D_HID; k++)
            acc = fmaf(sx[local * D_HID + k], sW[k * D_OUT + j], acc);
        g_h2[node * D_OUT + j] = acc;
    }
}

// ---------------------------------------------------------------------------
// 7) gather layer 2: a2 = sum h2[src]*norm + h2*dinv^2 + b2
//    8 threads per node (float4 over 32 cols), 32 nodes per block.
// ---------------------------------------------------------------------------
__global__ void k_gather2(const float* __restrict__ b2, int n) {
    int t    = threadIdx.x & 7;
    int grp  = threadIdx.x >> 3;
    int node = blockIdx.x * 32 + grp;
    if (node >= n) return;
    int beg = g_off[node];
    int end = beg + g_cnt[node];
    float4 acc = make_float4(0.f, 0.f, 0.f, 0.f);
    for (int i = beg; i < end; i++) {
        int   s = __ldg(&g_csr_src[i]);
        float w = __ldg(&g_csr_norm[i]);
        float4 v = *reinterpret_cast<const float4*>(g_h2 + s * D_OUT + t * 4);
        acc.x = fmaf(v.x, w, acc.x);
        acc.y = fmaf(v.y, w, acc.y);
        acc.z = fmaf(v.z, w, acc.z);
        acc.w = fmaf(v.w, w, acc.w);
    }
    float di = g_dinv[node];
    float d2 = di * di;
    float4 self = *reinterpret_cast<const float4*>(g_h2 + node * D_OUT + t * 4);
    float4 bb   = *reinterpret_cast<const float4*>(b2 + t * 4);
    acc.x = fmaf(self.x, d2, acc.x) + bb.x;
    acc.y = fmaf(self.y, d2, acc.y) + bb.y;
    acc.z = fmaf(self.z, d2, acc.z) + bb.z;
    acc.w = fmaf(self.w, d2, acc.w) + bb.w;
    *reinterpret_cast<float4*>(g_a2 + node * D_OUT + t * 4) = acc;
}

// ---------------------------------------------------------------------------
// 8) per-edge logits: 8 threads/edge, float4 loads + shuffle reduce
// ---------------------------------------------------------------------------
__global__ void k_logits(float* __restrict__ out, int E) {
    int idx = blockIdx.x * blockDim.x + threadIdx.x;
    int e = idx >> 3;
    int q = idx & 7;
    if (e >= E) return;
    int s = g_src[e];
    int d = g_dst[e];
    float4 vs = *reinterpret_cast<const float4*>(g_a2 + s * D_OUT + q * 4);
    float4 vd = *reinterpret_cast<const float4*>(g_a2 + d * D_OUT + q * 4);
    float p = vs.x * vd.x + vs.y * vd.y + vs.z * vd.z + vs.w * vd.w;
    p += __shfl_xor_sync(0xffffffffu, p, 1);
    p += __shfl_xor_sync(0xffffffffu, p, 2);
    p += __shfl_xor_sync(0xffffffffu, p, 4);
    if (q == 0) out[e] = p;
}

// ---------------------------------------------------------------------------
extern "C" void kernel_launch(void* const* d_in, const int* in_sizes, int n_in,
                              void* d_out, int out_size) {
    const float* x   = (const float*)d_in[0];
    const void*  ei  = d_in[1];
    const float* W1  = (const float*)d_in[2];
    const float* b1  = (const float*)d_in[3];
    const float* W2  = (const float*)d_in[4];
    const float* b2  = (const float*)d_in[5];
    float*       out = (float*)d_out;

    int N = in_sizes[0] / D_IN; if (N > N_NODES) N = N_NODES;
    int E = in_sizes[1] / 2;    if (E > MAX_E)   E = MAX_E;
    const int T = 256;

    // index conversion
    k_detect<<<1, 32>>>(ei);
    k_convert<<<(2 * E + T - 1) / T, T>>>(ei, E);

    // degree histogram + dinv
    k_cnt_init<<<(N + T - 1) / T, T>>>(N);
    k_deg_accum<<<(E + T - 1) / T, T>>>(E);
    k_dinv<<<(N + T - 1) / T, T>>>(N);

    // CSR build
    k_scan_a<<<NCHUNK / T, T>>>(N);
    k_scan_b<<<1, 256>>>();
    k_scan_c<<<NCHUNK / T, T>>>(N);
    k_csr_fill<<<(E + T - 1) / T, T>>>(E);

    // layer 1
    k_gemm1<<<(N + 3) / 4, T>>>(x, W1, N);
    k_gather1<<<(N + 15) / 16, T>>>(b1, N);

    // layer 2
    k_gemm2<<<(N + 7) / 8, T>>>(W2, N);
    k_gather2<<<(N + 31) / 32, T>>>(b2, N);

    // edge logits
    {
        long long total = (long long)E * 8;
        k_logits<<<(int)((total + T - 1) / T), T>>>(out, E);
    }
}

// round 6
// speedup vs baseline: 1.1700x; 1.0464x over previous
#include <cuda_runtime.h>
#include <cuda_fp16.h>

// GCN link predictor, CSR gather formulation with fp16 gather rows:
//   deg/dinv from dst histogram (+1 self loop); CSR grouped by dst,
//   payload packed (src, norm) as float2.
//   h1 = x @ W1 (fp32 + fp16 copy); a1 = relu( sum h1h[src]*norm + h1*dinv^2 + b1 )
//   h2 = a1 @ W2 (fp32 + fp16 copy); a2 =       sum h2h[src]*norm + h2*dinv^2 + b2
//   logits[e] = dot(a2[src], a2[dst])   (fp32)
//
// NOTE: __device__ scratch arrays are ONLY referenced inside device code
// (host-side use of the symbol is UB and silently corrupts via ATS on GB300).

#define N_NODES 100000
#define MAX_E   1600000
#define D_IN    32
#define D_HID   64
#define D_OUT   32

#define NCHUNK  2048
#define CHUNK   ((N_NODES + NCHUNK - 1) / NCHUNK)

__device__ __align__(16) int    g_cnt [N_NODES];
__device__ __align__(16) int    g_off [N_NODES];
__device__ __align__(16) float  g_dinv[N_NODES];
__device__ __align__(16) float  g_h1  [N_NODES * D_HID];
__device__ __align__(16) __half g_h1h [N_NODES * D_HID];
__device__ __align__(16) float  g_a1  [N_NODES * D_HID];
__device__ __align__(16) float  g_h2  [N_NODES * D_OUT];
__device__ __align__(16) __half g_h2h [N_NODES * D_OUT];
__device__ __align__(16) float  g_a2  [N_NODES * D_OUT];
__device__ __align__(16) int    g_src [MAX_E];
__device__ __align__(16) int    g_dst [MAX_E];
__device__ __align__(16) int    g_pos [MAX_E];
__device__ __align__(16) float2 g_csr [MAX_E];   // (.x = src bits, .y = norm)
__device__ __align__(16) int    g_part[NCHUNK];
__device__ int g_is64;

// ---------------------------------------------------------------------------
// 0) dtype detect + index conversion
// ---------------------------------------------------------------------------
__global__ void k_detect(const void* __restrict__ ei) {
    if (threadIdx.x == 0 && blockIdx.x == 0) {
        const long long* p = (const long long*)ei;
        int is64 = 1;
        #pragma unroll
        for (int i = 0; i < 8; i++) {
            long long v = p[i];
            if (v < 0 || v >= N_NODES) is64 = 0;
        }
        g_is64 = is64;
    }
}

__global__ void k_convert(const void* __restrict__ ei, int E) {
    int i = blockIdx.x * blockDim.x + threadIdx.x;
    if (i >= 2 * E) return;
    int v;
    if (g_is64) v = (int)((const long long*)ei)[i];
    else        v = ((const int*)ei)[i];
    v = min(max(v, 0), N_NODES - 1);
    if (i < E) g_src[i] = v;
    else       g_dst[i - E] = v;
}

// ---------------------------------------------------------------------------
// 1) degree histogram (records per-edge slot) + dinv
// ---------------------------------------------------------------------------
__global__ void k_cnt_init(int n) {
    int i = blockIdx.x * blockDim.x + threadIdx.x;
    if (i < n) g_cnt[i] = 0;
}

__global__ void k_deg_accum(int E) {
    int e = blockIdx.x * blockDim.x + threadIdx.x;
    if (e < E) g_pos[e] = atomicAdd(&g_cnt[g_dst[e]], 1);
}

__global__ void k_dinv(int n) {
    int i = blockIdx.x * blockDim.x + threadIdx.x;
    if (i < n) g_dinv[i] = rsqrtf((float)(g_cnt[i] + 1));
}

// ---------------------------------------------------------------------------
// 2) exclusive scan of g_cnt -> g_off
// ---------------------------------------------------------------------------
__global__ void k_scan_a(int n) {
    int c = blockIdx.x * blockDim.x + threadIdx.x;
    if (c >= NCHUNK) return;
    int beg = c * CHUNK, end = min(beg + CHUNK, n);
    int s = 0;
    for (int i = beg; i < end; i++) s += g_cnt[i];
    g_part[c] = s;
}

__global__ void k_scan_b() {
    __shared__ int sh[256];
    int t = threadIdx.x;
    int base = t * 8;
    int loc[8]; int sum = 0;
    #pragma unroll
    for (int i = 0; i < 8; i++) { loc[i] = g_part[base + i]; sum += loc[i]; }
    sh[t] = sum;
    __syncthreads();
    #pragma unroll
    for (int d = 1; d < 256; d <<= 1) {
        int v = (t >= d) ? sh[t - d] : 0;
        __syncthreads();
        sh[t] += v;
        __syncthreads();
    }
    int run = (t == 0) ? 0 : sh[t - 1];
    #pragma unroll
    for (int i = 0; i < 8; i++) { int tmp = loc[i]; g_part[base + i] = run; run += tmp; }
}

__global__ void k_scan_c(int n) {
    int c = blockIdx.x * blockDim.x + threadIdx.x;
    if (c >= NCHUNK) return;
    int beg = c * CHUNK, end = min(beg + CHUNK, n);
    int run = g_part[c];
    for (int i = beg; i < end; i++) { g_off[i] = run; run += g_cnt[i]; }
}

// ---------------------------------------------------------------------------
// 3) CSR fill, atomic-free (uses recorded slot)
// ---------------------------------------------------------------------------
__global__ void k_csr_fill(int E) {
    int e = blockIdx.x * blockDim.x + threadIdx.x;
    if (e >= E) return;
    int s = g_src[e];
    int d = g_dst[e];
    int pos = g_off[d] + g_pos[e];
    g_csr[pos] = make_float2(__int_as_float(s), g_dinv[s] * g_dinv[d]);
}

// ---------------------------------------------------------------------------
// 4) GEMM1: h1 = x @ W1 (fp32 + fp16 copy)
// ---------------------------------------------------------------------------
__global__ void k_gemm1(const float* __restrict__ x, const float* __restrict__ W1, int n) {
    __shared__ float sW[D_IN * D_HID];
    __shared__ float sx[4 * D_IN];
    int tid = threadIdx.x;
    for (int i = tid; i < D_IN * D_HID; i += 256) sW[i] = W1[i];
    int node0 = blockIdx.x * 4;
    if (tid < 4 * D_IN) {
        int nn = node0 + tid / D_IN;
        sx[tid] = (nn < n) ? x[nn * D_IN + (tid % D_IN)] : 0.0f;
    }
    __syncthreads();
    int local = tid >> 6;
    int j     = tid & 63;
    int node  = node0 + local;
    if (node < n) {
        float acc = 0.0f;
        #pragma unroll
        for (int k = 0; k < D_IN; k++)
            acc = fmaf(sx[local * D_IN + k], sW[k * D_HID + j], acc);
        g_h1 [node * D_HID + j] = acc;
        g_h1h[node * D_HID + j] = __float2half(acc);
    }
}

// ---------------------------------------------------------------------------
// fp16 row accumulate helper: uint4 = 8 halves
// ---------------------------------------------------------------------------
__device__ __forceinline__ void add_row8(float* acc, uint4 r, float w) {
    __half2* h = reinterpret_cast<__half2*>(&r);
    #pragma unroll
    for (int k = 0; k < 4; k++) {
        float2 f = __half22float2(h[k]);
        acc[2 * k + 0] = fmaf(f.x, w, acc[2 * k + 0]);
        acc[2 * k + 1] = fmaf(f.y, w, acc[2 * k + 1]);
    }
}

// ---------------------------------------------------------------------------
// 5) gather layer 1: 8 threads/node over 64 cols (fp16 rows), 2-way unroll
// ---------------------------------------------------------------------------
__global__ void k_gather1(const float* __restrict__ b1, int n) {
    int t    = threadIdx.x & 7;
    int grp  = threadIdx.x >> 3;
    int node = blockIdx.x * 32 + grp;
    if (node >= n) return;
    int beg = g_off[node];
    int end = beg + g_cnt[node];
    const uint4* rows = reinterpret_cast<const uint4*>(g_h1h);  // 8 uint4 / row
    float acc[8];
    #pragma unroll
    for (int k = 0; k < 8; k++) acc[k] = 0.0f;
    int i = beg;
    for (; i + 2 <= end; i += 2) {
        float2 e0 = g_csr[i];
        float2 e1 = g_csr[i + 1];
        uint4 r0 = rows[__float_as_int(e0.x) * 8 + t];
        uint4 r1 = rows[__float_as_int(e1.x) * 8 + t];
        add_row8(acc, r0, e0.y);
        add_row8(acc, r1, e1.y);
    }
    if (i < end) {
        float2 e0 = g_csr[i];
        uint4 r0 = rows[__float_as_int(e0.x) * 8 + t];
        add_row8(acc, r0, e0.y);
    }
    float di = g_dinv[node];
    float d2 = di * di;
    const float* selfp = g_h1 + node * D_HID + t * 8;
    const float* bp    = b1 + t * 8;
    float* outp        = g_a1 + node * D_HID + t * 8;
    #pragma unroll
    for (int half = 0; half < 2; half++) {
        float4 s4 = *reinterpret_cast<const float4*>(selfp + half * 4);
        float4 b4 = *reinterpret_cast<const float4*>(bp + half * 4);
        float4 o;
        o.x = fmaxf(fmaf(s4.x, d2, acc[half * 4 + 0]) + b4.x, 0.f);
        o.y = fmaxf(fmaf(s4.y, d2, acc[half * 4 + 1]) + b4.y, 0.f);
        o.z = fmaxf(fmaf(s4.z, d2, acc[half * 4 + 2]) + b4.z, 0.f);
        o.w = fmaxf(fmaf(s4.w, d2, acc[half * 4 + 3]) + b4.w, 0.f);
        *reinterpret_cast<float4*>(outp + half * 4) = o;
    }
}

// ---------------------------------------------------------------------------
// 6) GEMM2: h2 = a1 @ W2 (fp32 + fp16 copy)
// ---------------------------------------------------------------------------
__global__ void k_gemm2(const float* __restrict__ W2, int n) {
    __shared__ float sW[D_HID * D_OUT];
    __shared__ float sx[8 * D_HID];
    int tid = threadIdx.x;
    for (int i = tid; i < D_HID * D_OUT; i += 256) sW[i] = W2[i];
    int node0 = blockIdx.x * 8;
    for (int i = tid; i < 8 * D_HID; i += 256) {
        int nn = node0 + i / D_HID;
        sx[i] = (nn < n) ? g_a1[nn * D_HID + (i % D_HID)] : 0.0f;
    }
    __syncthreads();
    int local = tid >> 5;
    int j     = tid & 31;
    int node  = node0 + local;
    if (node < n) {
        float acc = 0.0f;
        #pragma unroll
        for (int k = 0; k < D_HID; k++)
            acc = fmaf(sx[local * D_HID + k], sW[k * D_OUT + j], acc);
        g_h2 [node * D_OUT + j] = acc;
        g_h2h[node * D_OUT + j] = __float2half(acc);
    }
}

// ---------------------------------------------------------------------------
// 7) gather layer 2: 4 threads/node over 32 cols (fp16 rows), 2-way unroll
// ---------------------------------------------------------------------------
__global__ void k_gather2(const float* __restrict__ b2, int n) {
    int t    = threadIdx.x & 3;
    int grp  = threadIdx.x >> 2;
    int node = blockIdx.x * 64 + grp;
    if (node >= n) return;
    int beg = g_off[node];
    int end = beg + g_cnt[node];
    const uint4* rows = reinterpret_cast<const uint4*>(g_h2h);  // 4 uint4 / row
    float acc[8];
    #pragma unroll
    for (int k = 0; k < 8; k++) acc[k] = 0.0f;
    int i = beg;
    for (; i + 2 <= end; i += 2) {
        float2 e0 = g_csr[i];
        float2 e1 = g_csr[i + 1];
        uint4 r0 = rows[__float_as_int(e0.x) * 4 + t];
        uint4 r1 = rows[__float_as_int(e1.x) * 4 + t];
        add_row8(acc, r0, e0.y);
        add_row8(acc, r1, e1.y);
    }
    if (i < end) {
        float2 e0 = g_csr[i];
        uint4 r0 = rows[__float_as_int(e0.x) * 4 + t];
        add_row8(acc, r0, e0.y);
    }
    float di = g_dinv[node];
    float d2 = di * di;
    const float* selfp = g_h2 + node * D_OUT + t * 8;
    const float* bp    = b2 + t * 8;
    float* outp        = g_a2 + node * D_OUT + t * 8;
    #pragma unroll
    for (int half = 0; half < 2; half++) {
        float4 s4 = *reinterpret_cast<const float4*>(selfp + half * 4);
        float4 b4 = *reinterpret_cast<const float4*>(bp + half * 4);
        float4 o;
        o.x = fmaf(s4.x, d2, acc[half * 4 + 0]) + b4.x;
        o.y = fmaf(s4.y, d2, acc[half * 4 + 1]) + b4.y;
        o.z = fmaf(s4.z, d2, acc[half * 4 + 2]) + b4.z;
        o.w = fmaf(s4.w, d2, acc[half * 4 + 3]) + b4.w;
        *reinterpret_cast<float4*>(outp + half * 4) = o;
    }
}

// ---------------------------------------------------------------------------
// 8) per-edge logits: 8 threads/edge, fp32, float4 + shuffle reduce
// ---------------------------------------------------------------------------
__global__ void k_logits(float* __restrict__ out, int E) {
    int idx = blockIdx.x * blockDim.x + threadIdx.x;
    int e = idx >> 3;
    int q = idx & 7;
    if (e >= E) return;
    int s = g_src[e];
    int d = g_dst[e];
    float4 vs = *reinterpret_cast<const float4*>(g_a2 + s * D_OUT + q * 4);
    float4 vd = *reinterpret_cast<const float4*>(g_a2 + d * D_OUT + q * 4);
    float p = vs.x * vd.x + vs.y * vd.y + vs.z * vd.z + vs.w * vd.w;
    p += __shfl_xor_sync(0xffffffffu, p, 1);
    p += __shfl_xor_sync(0xffffffffu, p, 2);
    p += __shfl_xor_sync(0xffffffffu, p, 4);
    if (q == 0) out[e] = p;
}

// ---------------------------------------------------------------------------
extern "C" void kernel_launch(void* const* d_in, const int* in_sizes, int n_in,
                              void* d_out, int out_size) {
    const float* x   = (const float*)d_in[0];
    const void*  ei  = d_in[1];
    const float* W1  = (const float*)d_in[2];
    const float* b1  = (const float*)d_in[3];
    const float* W2  = (const float*)d_in[4];
    const float* b2  = (const float*)d_in[5];
    float*       out = (float*)d_out;

    int N = in_sizes[0] / D_IN; if (N > N_NODES) N = N_NODES;
    int E = in_sizes[1] / 2;    if (E > MAX_E)   E = MAX_E;
    const int T = 256;

    k_detect<<<1, 32>>>(ei);
    k_convert<<<(2 * E + T - 1) / T, T>>>(ei, E);

    k_cnt_init<<<(N + T - 1) / T, T>>>(N);
    k_deg_accum<<<(E + T - 1) / T, T>>>(E);
    k_dinv<<<(N + T - 1) / T, T>>>(N);

    k_scan_a<<<NCHUNK / T, T>>>(N);
    k_scan_b<<<1, 256>>>();
    k_scan_c<<<NCHUNK / T, T>>>(N);
    k_csr_fill<<<(E + T - 1) / T, T>>>(E);

    k_gemm1<<<(N + 3) / 4, T>>>(x, W1, N);
    k_gather1<<<(N + 31) / 32, T>>>(b1, N);

    k_gemm2<<<(N + 7) / 8, T>>>(W2, N);
    k_gather2<<<(N + 63) / 64, T>>>(b2, N);

    {
        long long total = (long long)E * 8;
        k_logits<<<(int)((total + T - 1) / T), T>>>(out, E);
    }
}

// round 7
// speedup vs baseline: 1.2200x; 1.0427x over previous
#include <cuda_runtime.h>
#include <cuda_fp16.h>

// GCN link predictor, CSR gather formulation, fp16 gather rows + fp16 a2:
//   deg/dinv from dst histogram (+1 self loop); CSR grouped by dst,
//   payload packed (src, norm) as float2.
//   h1 = x @ W1 (fp32 + fp16); a1 = relu( sum h1h[src]*norm + h1*dinv^2 + b1 )
//   h2 = a1 @ W2 (fp32 + fp16); a2h = fp16( sum h2h[src]*norm + h2*dinv^2 + b2 )
//   logits[e] = dot(a2h[src], a2h[dst]) accumulated in fp32
//
// NOTE: __device__ scratch arrays are ONLY referenced inside device code
// (host-side use of the symbol is UB and silently corrupts via ATS on GB300).

#define N_NODES 100000
#define MAX_E   1600000
#define D_IN    32
#define D_HID   64
#define D_OUT   32

#define NCHUNK  2048
#define CHUNK   ((N_NODES + NCHUNK - 1) / NCHUNK)

__device__ __align__(16) int    g_cnt [N_NODES];
__device__ __align__(16) int    g_off [N_NODES];
__device__ __align__(16) float  g_dinv[N_NODES];
__device__ __align__(16) float  g_h1  [N_NODES * D_HID];
__device__ __align__(16) __half g_h1h [N_NODES * D_HID];
__device__ __align__(16) float  g_a1  [N_NODES * D_HID];
__device__ __align__(16) float  g_h2  [N_NODES * D_OUT];
__device__ __align__(16) __half g_h2h [N_NODES * D_OUT];
__device__ __align__(16) __half g_a2h [N_NODES * D_OUT];
__device__ __align__(16) int    g_src [MAX_E];
__device__ __align__(16) int    g_dst [MAX_E];
__device__ __align__(16) int    g_pos [MAX_E];
__device__ __align__(16) float2 g_csr [MAX_E];   // (.x = src bits, .y = norm)
__device__ __align__(16) int    g_part[NCHUNK];
__device__ int g_is64;

// ---------------------------------------------------------------------------
// 0) dtype detect
// ---------------------------------------------------------------------------
__global__ void k_detect(const void* __restrict__ ei) {
    if (threadIdx.x == 0 && blockIdx.x == 0) {
        const long long* p = (const long long*)ei;
        int is64 = 1;
        #pragma unroll
        for (int i = 0; i < 8; i++) {
            long long v = p[i];
            if (v < 0 || v >= N_NODES) is64 = 0;
        }
        g_is64 = is64;
    }
}

__global__ void k_cnt_init(int n) {
    int i = blockIdx.x * blockDim.x + threadIdx.x;
    if (i < n) g_cnt[i] = 0;
}

// ---------------------------------------------------------------------------
// 1) convert indices + fused degree histogram (records per-edge slot)
// ---------------------------------------------------------------------------
__global__ void k_convert(const void* __restrict__ ei, int E) {
    int i = blockIdx.x * blockDim.x + threadIdx.x;
    if (i >= 2 * E) return;
    int v;
    if (g_is64) v = (int)((const long long*)ei)[i];
    else        v = ((const int*)ei)[i];
    v = min(max(v, 0), N_NODES - 1);
    if (i < E) {
        g_src[i] = v;
    } else {
        int e = i - E;
        g_dst[e] = v;
        g_pos[e] = atomicAdd(&g_cnt[v], 1);
    }
}

// ---------------------------------------------------------------------------
// 2) exclusive scan of g_cnt -> g_off (+ fused dinv)
// ---------------------------------------------------------------------------
__global__ void k_scan_a(int n) {
    int c = blockIdx.x * blockDim.x + threadIdx.x;
    if (c >= NCHUNK) return;
    int beg = c * CHUNK, end = min(beg + CHUNK, n);
    int s = 0;
    for (int i = beg; i < end; i++) s += g_cnt[i];
    g_part[c] = s;
}

__global__ void k_scan_b() {
    __shared__ int sh[256];
    int t = threadIdx.x;
    int base = t * 8;
    int loc[8]; int sum = 0;
    #pragma unroll
    for (int i = 0; i < 8; i++) { loc[i] = g_part[base + i]; sum += loc[i]; }
    sh[t] = sum;
    __syncthreads();
    #pragma unroll
    for (int d = 1; d < 256; d <<= 1) {
        int v = (t >= d) ? sh[t - d] : 0;
        __syncthreads();
        sh[t] += v;
        __syncthreads();
    }
    int run = (t == 0) ? 0 : sh[t - 1];
    #pragma unroll
    for (int i = 0; i < 8; i++) { int tmp = loc[i]; g_part[base + i] = run; run += tmp; }
}

__global__ void k_scan_c(int n) {
    int c = blockIdx.x * blockDim.x + threadIdx.x;
    if (c >= NCHUNK) return;
    int beg = c * CHUNK, end = min(beg + CHUNK, n);
    int run = g_part[c];
    for (int i = beg; i < end; i++) {
        int cnt = g_cnt[i];
        g_off[i] = run;
        run += cnt;
        g_dinv[i] = rsqrtf((float)(cnt + 1));
    }
}

// ---------------------------------------------------------------------------
// 3) CSR fill, atomic-free
// ---------------------------------------------------------------------------
__global__ void k_csr_fill(int E) {
    int e = blockIdx.x * blockDim.x + threadIdx.x;
    if (e >= E) return;
    int s = g_src[e];
    int d = g_dst[e];
    int pos = g_off[d] + g_pos[e];
    g_csr[pos] = make_float2(__int_as_float(s), g_dinv[s] * g_dinv[d]);
}

// ---------------------------------------------------------------------------
// 4) GEMM1: h1 = x @ W1 (fp32 + fp16 copy)
// ---------------------------------------------------------------------------
__global__ void k_gemm1(const float* __restrict__ x, const float* __restrict__ W1, int n) {
    __shared__ float sW[D_IN * D_HID];
    __shared__ float sx[4 * D_IN];
    int tid = threadIdx.x;
    for (int i = tid; i < D_IN * D_HID; i += 256) sW[i] = W1[i];
    int node0 = blockIdx.x * 4;
    if (tid < 4 * D_IN) {
        int nn = node0 + tid / D_IN;
        sx[tid] = (nn < n) ? x[nn * D_IN + (tid % D_IN)] : 0.0f;
    }
    __syncthreads();
    int local = tid >> 6;
    int j     = tid & 63;
    int node  = node0 + local;
    if (node < n) {
        float acc = 0.0f;
        #pragma unroll
        for (int k = 0; k < D_IN; k++)
            acc = fmaf(sx[local * D_IN + k], sW[k * D_HID + j], acc);
        g_h1 [node * D_HID + j] = acc;
        g_h1h[node * D_HID + j] = __float2half(acc);
    }
}

// ---------------------------------------------------------------------------
// fp16 accumulate helpers
// ---------------------------------------------------------------------------
__device__ __forceinline__ void add_row8(float* acc, uint4 r, float w) {
    __half2* h = reinterpret_cast<__half2*>(&r);
    #pragma unroll
    for (int k = 0; k < 4; k++) {
        float2 f = __half22float2(h[k]);
        acc[2 * k + 0] = fmaf(f.x, w, acc[2 * k + 0]);
        acc[2 * k + 1] = fmaf(f.y, w, acc[2 * k + 1]);
    }
}

__device__ __forceinline__ void add_row4(float* acc, uint2 r, float w) {
    __half2* h = reinterpret_cast<__half2*>(&r);
    #pragma unroll
    for (int k = 0; k < 2; k++) {
        float2 f = __half22float2(h[k]);
        acc[2 * k + 0] = fmaf(f.x, w, acc[2 * k + 0]);
        acc[2 * k + 1] = fmaf(f.y, w, acc[2 * k + 1]);
    }
}

// ---------------------------------------------------------------------------
// 5) gather layer 1: 8 threads/node, 8 cols each; shuffle-batched edges
//    (coalesced csr loads, MLP=8 row loads per batch)
// ---------------------------------------------------------------------------
__global__ void k_gather1(const float* __restrict__ b1, int n) {
    int lane = threadIdx.x & 31;
    int t    = lane & 7;
    int node = blockIdx.x * 32 + (threadIdx.x >> 3);
    if (node >= n) return;
    unsigned gmask = 0xFFu << (lane & 24);
    int beg = g_off[node];
    int end = beg + g_cnt[node];
    const uint4* rows = reinterpret_cast<const uint4*>(g_h1h);  // 8 uint4 / row
    float acc[8];
    #pragma unroll
    for (int k = 0; k < 8; k++) acc[k] = 0.0f;
    for (int i = beg; i < end; i += 8) {
        float2 e = (i + t < end) ? g_csr[i + t] : make_float2(0.f, 0.f);
        #pragma unroll
        for (int k = 0; k < 8; k++) {
            if (i + k >= end) break;
            float ex = __shfl_sync(gmask, e.x, k, 8);
            float ey = __shfl_sync(gmask, e.y, k, 8);
            uint4 r = rows[__float_as_int(ex) * 8 + t];
            add_row8(acc, r, ey);
        }
    }
    float di = g_dinv[node];
    float d2 = di * di;
    const float* selfp = g_h1 + node * D_HID + t * 8;
    const float* bp    = b1 + t * 8;
    float* outp        = g_a1 + node * D_HID + t * 8;
    #pragma unroll
    for (int half = 0; half < 2; half++) {
        float4 s4 = *reinterpret_cast<const float4*>(selfp + half * 4);
        float4 b4 = *reinterpret_cast<const float4*>(bp + half * 4);
        float4 o;
        o.x = fmaxf(fmaf(s4.x, d2, acc[half * 4 + 0]) + b4.x, 0.f);
        o.y = fmaxf(fmaf(s4.y, d2, acc[half * 4 + 1]) + b4.y, 0.f);
        o.z = fmaxf(fmaf(s4.z, d2, acc[half * 4 + 2]) + b4.z, 0.f);
        o.w = fmaxf(fmaf(s4.w, d2, acc[half * 4 + 3]) + b4.w, 0.f);
        *reinterpret_cast<float4*>(outp + half * 4) = o;
    }
}

// ---------------------------------------------------------------------------
// 6) GEMM2: h2 = a1 @ W2 (fp32 + fp16 copy)
// ---------------------------------------------------------------------------
__global__ void k_gemm2(const float* __restrict__ W2, int n) {
    __shared__ float sW[D_HID * D_OUT];
    __shared__ float sx[8 * D_HID];
    int tid = threadIdx.x;
    for (int i = tid; i < D_HID * D_OUT; i += 256) sW[i] = W2[i];
    int node0 = blockIdx.x * 8;
    for (int i = tid; i < 8 * D_HID; i += 256) {
        int nn = node0 + i / D_HID;
        sx[i] = (nn < n) ? g_a1[nn * D_HID + (i % D_HID)] : 0.0f;
    }
    __syncthreads();
    int local = tid >> 5;
    int j     = tid & 31;
    int node  = node0 + local;
    if (node < n) {
        float acc = 0.0f;
        #pragma unroll
        for (int k = 0; k < D_HID; k++)
            acc = fmaf(sx[local * D_HID + k], sW[k * D_OUT + j], acc);
        g_h2 [node * D_OUT + j] = acc;
        g_h2h[node * D_OUT + j] = __float2half(acc);
    }
}

// ---------------------------------------------------------------------------
// 7) gather layer 2: 8 threads/node, 4 cols each; shuffle-batched edges.
//    Output a2 ONLY as fp16 (feeds logits only).
// ---------------------------------------------------------------------------
__global__ void k_gather2(const float* __restrict__ b2, int n) {
    int lane = threadIdx.x & 31;
    int t    = lane & 7;
    int node = blockIdx.x * 32 + (threadIdx.x >> 3);
    if (node >= n) return;
    unsigned gmask = 0xFFu << (lane & 24);
    int beg = g_off[node];
    int end = beg + g_cnt[node];
    const uint2* rows = reinterpret_cast<const uint2*>(g_h2h);  // 8 uint2 / row
    float acc[4];
    #pragma unroll
    for (int k = 0; k < 4; k++) acc[k] = 0.0f;
    for (int i = beg; i < end; i += 8) {
        float2 e = (i + t < end) ? g_csr[i + t] : make_float2(0.f, 0.f);
        #pragma unroll
        for (int k = 0; k < 8; k++) {
            if (i + k >= end) break;
            float ex = __shfl_sync(gmask, e.x, k, 8);
            float ey = __shfl_sync(gmask, e.y, k, 8);
            uint2 r = rows[__float_as_int(ex) * 8 + t];
            add_row4(acc, r, ey);
        }
    }
    float di = g_dinv[node];
    float d2 = di * di;
    float4 s4 = *reinterpret_cast<const float4*>(g_h2 + node * D_OUT + t * 4);
    float4 b4 = *reinterpret_cast<const float4*>(b2 + t * 4);
    float o0 = fmaf(s4.x, d2, acc[0]) + b4.x;
    float o1 = fmaf(s4.y, d2, acc[1]) + b4.y;
    float o2 = fmaf(s4.z, d2, acc[2]) + b4.z;
    float o3 = fmaf(s4.w, d2, acc[3]) + b4.w;
    __half2 h0 = __floats2half2_rn(o0, o1);
    __half2 h1 = __floats2half2_rn(o2, o3);
    uint2 packed;
    packed.x = *reinterpret_cast<unsigned*>(&h0);
    packed.y = *reinterpret_cast<unsigned*>(&h1);
    reinterpret_cast<uint2*>(g_a2h)[node * 8 + t] = packed;
}

// ---------------------------------------------------------------------------
// 8) per-edge logits: 4 threads/edge, fp16 rows (16B loads), fp32 dot
// ---------------------------------------------------------------------------
__global__ void k_logits(float* __restrict__ out, int E) {
    int idx = blockIdx.x * blockDim.x + threadIdx.x;
    int e = idx >> 2;
    int q = idx & 3;
    if (e >= E) return;
    int s = g_src[e];
    int d = g_dst[e];
    const uint4* rows = reinterpret_cast<const uint4*>(g_a2h);  // 4 uint4 / row
    uint4 vs = rows[s * 4 + q];
    uint4 vd = rows[d * 4 + q];
    __half2* hs = reinterpret_cast<__half2*>(&vs);
    __half2* hd = reinterpret_cast<__half2*>(&vd);
    float p = 0.0f;
    #pragma unroll
    for (int k = 0; k < 4; k++) {
        float2 fs = __half22float2(hs[k]);
        float2 fd = __half22float2(hd[k]);
        p = fmaf(fs.x, fd.x, p);
        p = fmaf(fs.y, fd.y, p);
    }
    p += __shfl_xor_sync(0xffffffffu, p, 1);
    p += __shfl_xor_sync(0xffffffffu, p, 2);
    if (q == 0) out[e] = p;
}

// ---------------------------------------------------------------------------
extern "C" void kernel_launch(void* const* d_in, const int* in_sizes, int n_in,
                              void* d_out, int out_size) {
    const float* x   = (const float*)d_in[0];
    const void*  ei  = d_in[1];
    const float* W1  = (const float*)d_in[2];
    const float* b1  = (const float*)d_in[3];
    const float* W2  = (const float*)d_in[4];
    const float* b2  = (const float*)d_in[5];
    float*       out = (float*)d_out;

    int N = in_sizes[0] / D_IN; if (N > N_NODES) N = N_NODES;
    int E = in_sizes[1] / 2;    if (E > MAX_E)   E = MAX_E;
    const int T = 256;

    k_detect<<<1, 32>>>(ei);
    k_cnt_init<<<(N + T - 1) / T, T>>>(N);
    k_convert<<<(2 * E + T - 1) / T, T>>>(ei, E);

    k_scan_a<<<NCHUNK / T, T>>>(N);
    k_scan_b<<<1, 256>>>();
    k_scan_c<<<NCHUNK / T, T>>>(N);
    k_csr_fill<<<(E + T - 1) / T, T>>>(E);

    k_gemm1<<<(N + 3) / 4, T>>>(x, W1, N);
    k_gather1<<<(N + 31) / 32, T>>>(b1, N);

    k_gemm2<<<(N + 7) / 8, T>>>(W2, N);
    k_gather2<<<(N + 31) / 32, T>>>(b2, N);

    {
        long long total = (long long)E * 4;
        k_logits<<<(int)((total + T - 1) / T), T>>>(out, E);
    }
}

// round 8
// speedup vs baseline: 1.2952x; 1.0617x over previous
#include <cuda_runtime.h>
#include <cuda_fp16.h>

// GCN link predictor, CSR gather formulation, fp16 gather rows + fp16 a2:
//   h1 = x @ W1 (fp32 + fp16); a1 = relu( sum h1h[src]*norm + h1*dinv^2 + b1 )
//   h2 = a1 @ W2 (fp32 + fp16); a2h = fp16( sum h2h[src]*norm + h2*dinv^2 + b2 )
//   logits[e] = dot(a2h[src], a2h[dst]) accumulated in fp32
//
// NOTE: __device__ scratch arrays are ONLY referenced inside device code
// (host-side use of the symbol is UB and silently corrupts via ATS on GB300).

#define N_NODES 100000
#define MAX_E   1600000
#define D_IN    32
#define D_HID   64
#define D_OUT   32

#define CHW     128                              // elements per scan warp
#define NW      ((N_NODES + CHW - 1) / CHW)      // 782 scan warps
#define NPART   1024

__device__ __align__(16) int    g_cnt [N_NODES];
__device__ __align__(16) int    g_off [N_NODES];
__device__ __align__(16) float  g_dinv[N_NODES];
__device__ __align__(16) float  g_h1  [N_NODES * D_HID];
__device__ __align__(16) __half g_h1h [N_NODES * D_HID];
__device__ __align__(16) float  g_a1  [N_NODES * D_HID];
__device__ __align__(16) float  g_h2  [N_NODES * D_OUT];
__device__ __align__(16) __half g_h2h [N_NODES * D_OUT];
__device__ __align__(16) __half g_a2h [N_NODES * D_OUT];
__device__ __align__(16) int    g_src [MAX_E];
__device__ __align__(16) int    g_dst [MAX_E];
__device__ __align__(16) int    g_pos [MAX_E];
__device__ __align__(16) float2 g_csr [MAX_E];   // (.x = src bits, .y = norm)
__device__ __align__(16) int    g_part[NPART];
__device__ int g_is64;

// ---------------------------------------------------------------------------
// 0) init: zero counts + dtype detect (fused)
// ---------------------------------------------------------------------------
__global__ void k_init(const void* __restrict__ ei, int n) {
    int i = blockIdx.x * blockDim.x + threadIdx.x;
    if (i < n) g_cnt[i] = 0;
    if (i == 0) {
        const long long* p = (const long long*)ei;
        int is64 = 1;
        #pragma unroll
        for (int k = 0; k < 8; k++) {
            long long v = p[k];
            if (v < 0 || v >= N_NODES) is64 = 0;
        }
        g_is64 = is64;
    }
}

// ---------------------------------------------------------------------------
// 1) convert indices + fused degree histogram (records per-edge slot)
// ---------------------------------------------------------------------------
__global__ void k_convert(const void* __restrict__ ei, int E) {
    int i = blockIdx.x * blockDim.x + threadIdx.x;
    if (i >= 2 * E) return;
    int v;
    if (g_is64) v = (int)((const long long*)ei)[i];
    else        v = ((const int*)ei)[i];
    v = min(max(v, 0), N_NODES - 1);
    if (i < E) {
        g_src[i] = v;
    } else {
        int e = i - E;
        g_dst[e] = v;
        g_pos[e] = atomicAdd(&g_cnt[v], 1);
    }
}

// ---------------------------------------------------------------------------
// 2) warp-cooperative exclusive scan of g_cnt -> g_off (+ fused dinv)
// ---------------------------------------------------------------------------
__global__ void k_scan_a(int n) {     // one warp per CHW-element chunk, coalesced
    int w    = (blockIdx.x * blockDim.x + threadIdx.x) >> 5;
    int lane = threadIdx.x & 31;
    if (w >= NW) return;
    int base = w * CHW;
    int sum = 0;
    #pragma unroll
    for (int tile = 0; tile < CHW; tile += 32) {
        int i = base + tile + lane;
        sum += (i < n) ? g_cnt[i] : 0;
    }
    #pragma unroll
    for (int d = 16; d > 0; d >>= 1) sum += __shfl_down_sync(0xffffffffu, sum, d);
    if (lane == 0) g_part[w] = sum;
}

__global__ void k_scan_b() {          // 1 block, 256 threads; 4 parts/thread
    __shared__ int sh[256];
    int t = threadIdx.x;
    int base = t * 4;
    int loc[4]; int sum = 0;
    #pragma unroll
    for (int i = 0; i < 4; i++) {
        loc[i] = (base + i < NW) ? g_part[base + i] : 0;
        sum += loc[i];
    }
    sh[t] = sum;
    __syncthreads();
    #pragma unroll
    for (int d = 1; d < 256; d <<= 1) {
        int v = (t >= d) ? sh[t - d] : 0;
        __syncthreads();
        sh[t] += v;
        __syncthreads();
    }
    int run = (t == 0) ? 0 : sh[t - 1];
    #pragma unroll
    for (int i = 0; i < 4; i++) {
        int tmp = loc[i];
        if (base + i < NW) g_part[base + i] = run;
        run += tmp;
    }
}

__global__ void k_scan_c(int n) {     // warp-scan per chunk, coalesced
    int w    = (blockIdx.x * blockDim.x + threadIdx.x) >> 5;
    int lane = threadIdx.x & 31;
    if (w >= NW) return;
    int base = w * CHW;
    int run = g_part[w];
    #pragma unroll
    for (int tile = 0; tile < CHW; tile += 32) {
        int i = base + tile + lane;
        int c = (i < n) ? g_cnt[i] : 0;
        int sc = c;
        #pragma unroll
        for (int d = 1; d < 32; d <<= 1) {
            int v = __shfl_up_sync(0xffffffffu, sc, d);
            if (lane >= d) sc += v;
        }
        if (i < n) {
            g_off[i]  = run + sc - c;
            g_dinv[i] = rsqrtf((float)(c + 1));
        }
        run += __shfl_sync(0xffffffffu, sc, 31);
    }
}

// ---------------------------------------------------------------------------
// 3) CSR fill, atomic-free
// ---------------------------------------------------------------------------
__global__ void k_csr_fill(int E) {
    int e = blockIdx.x * blockDim.x + threadIdx.x;
    if (e >= E) return;
    int s = g_src[e];
    int d = g_dst[e];
    int pos = g_off[d] + g_pos[e];
    g_csr[pos] = make_float2(__int_as_float(s), g_dinv[s] * g_dinv[d]);
}

// ---------------------------------------------------------------------------
// 4) GEMM1: h1 = x @ W1 (fp32 + fp16 copy)
// ---------------------------------------------------------------------------
__global__ void k_gemm1(const float* __restrict__ x, const float* __restrict__ W1, int n) {
    __shared__ float sW[D_IN * D_HID];
    __shared__ float sx[4 * D_IN];
    int tid = threadIdx.x;
    for (int i = tid; i < D_IN * D_HID; i += 256) sW[i] = W1[i];
    int node0 = blockIdx.x * 4;
    if (tid < 4 * D_IN) {
        int nn = node0 + tid / D_IN;
        sx[tid] = (nn < n) ? x[nn * D_IN + (tid % D_IN)] : 0.0f;
    }
    __syncthreads();
    int local = tid >> 6;
    int j     = tid & 63;
    int node  = node0 + local;
    if (node < n) {
        float acc = 0.0f;
        #pragma unroll
        for (int k = 0; k < D_IN; k++)
            acc = fmaf(sx[local * D_IN + k], sW[k * D_HID + j], acc);
        g_h1 [node * D_HID + j] = acc;
        g_h1h[node * D_HID + j] = __float2half(acc);
    }
}

// ---------------------------------------------------------------------------
// fp16 accumulate helpers
// ---------------------------------------------------------------------------
__device__ __forceinline__ void add_row8(float* acc, uint4 r, float w) {
    __half2* h = reinterpret_cast<__half2*>(&r);
    #pragma unroll
    for (int k = 0; k < 4; k++) {
        float2 f = __half22float2(h[k]);
        acc[2 * k + 0] = fmaf(f.x, w, acc[2 * k + 0]);
        acc[2 * k + 1] = fmaf(f.y, w, acc[2 * k + 1]);
    }
}

__device__ __forceinline__ void add_row4(float* acc, uint2 r, float w) {
    __half2* h = reinterpret_cast<__half2*>(&r);
    #pragma unroll
    for (int k = 0; k < 2; k++) {
        float2 f = __half22float2(h[k]);
        acc[2 * k + 0] = fmaf(f.x, w, acc[2 * k + 0]);
        acc[2 * k + 1] = fmaf(f.y, w, acc[2 * k + 1]);
    }
}

// ---------------------------------------------------------------------------
// 5) gather layer 1: 8 threads/node, 8 cols each; shuffle-batched edges,
//    branch-free full batches + one tail batch
// ---------------------------------------------------------------------------
__global__ void k_gather1(const float* __restrict__ b1, int n) {
    int lane = threadIdx.x & 31;
    int t    = lane & 7;
    int node = blockIdx.x * 32 + (threadIdx.x >> 3);
    if (node >= n) return;
    unsigned gmask = 0xFFu << (lane & 24);
    int beg = g_off[node];
    int end = beg + g_cnt[node];
    const uint4* rows = reinterpret_cast<const uint4*>(g_h1h);  // 8 uint4 / row
    float acc[8];
    #pragma unroll
    for (int k = 0; k < 8; k++) acc[k] = 0.0f;
    int nfull = (end - beg) & ~7;
    int i = beg;
    for (; i < beg + nfull; i += 8) {
        float2 e = g_csr[i + t];
        #pragma unroll
        for (int k = 0; k < 8; k++) {
            float ex = __shfl_sync(gmask, e.x, k, 8);
            float ey = __shfl_sync(gmask, e.y, k, 8);
            uint4 r = rows[__float_as_int(ex) * 8 + t];
            add_row8(acc, r, ey);
        }
    }
    if (i < end) {
        float2 e = (i + t < end) ? g_csr[i + t] : make_float2(0.f, 0.f);
        int rem = end - i;
        #pragma unroll
        for (int k = 0; k < 8; k++) {
            if (k >= rem) break;
            float ex = __shfl_sync(gmask, e.x, k, 8);
            float ey = __shfl_sync(gmask, e.y, k, 8);
            uint4 r = rows[__float_as_int(ex) * 8 + t];
            add_row8(acc, r, ey);
        }
    }
    float di = g_dinv[node];
    float d2 = di * di;
    const float* selfp = g_h1 + node * D_HID + t * 8;
    const float* bp    = b1 + t * 8;
    float* outp        = g_a1 + node * D_HID + t * 8;
    #pragma unroll
    for (int half = 0; half < 2; half++) {
        float4 s4 = *reinterpret_cast<const float4*>(selfp + half * 4);
        float4 b4 = *reinterpret_cast<const float4*>(bp + half * 4);
        float4 o;
        o.x = fmaxf(fmaf(s4.x, d2, acc[half * 4 + 0]) + b4.x, 0.f);
        o.y = fmaxf(fmaf(s4.y, d2, acc[half * 4 + 1]) + b4.y, 0.f);
        o.z = fmaxf(fmaf(s4.z, d2, acc[half * 4 + 2]) + b4.z, 0.f);
        o.w = fmaxf(fmaf(s4.w, d2, acc[half * 4 + 3]) + b4.w, 0.f);
        *reinterpret_cast<float4*>(outp + half * 4) = o;
    }
}

// ---------------------------------------------------------------------------
// 6) GEMM2: h2 = a1 @ W2 (fp32 + fp16 copy)
// ---------------------------------------------------------------------------
__global__ void k_gemm2(const float* __restrict__ W2, int n) {
    __shared__ float sW[D_HID * D_OUT];
    __shared__ float sx[8 * D_HID];
    int tid = threadIdx.x;
    for (int i = tid; i < D_HID * D_OUT; i += 256) sW[i] = W2[i];
    int node0 = blockIdx.x * 8;
    for (int i = tid; i < 8 * D_HID; i += 256) {
        int nn = node0 + i / D_HID;
        sx[i] = (nn < n) ? g_a1[nn * D_HID + (i % D_HID)] : 0.0f;
    }
    __syncthreads();
    int local = tid >> 5;
    int j     = tid & 31;
    int node  = node0 + local;
    if (node < n) {
        float acc = 0.0f;
        #pragma unroll
        for (int k = 0; k < D_HID; k++)
            acc = fmaf(sx[local * D_HID + k], sW[k * D_OUT + j], acc);
        g_h2 [node * D_OUT + j] = acc;
        g_h2h[node * D_OUT + j] = __float2half(acc);
    }
}

// ---------------------------------------------------------------------------
// 7) gather layer 2: 8 threads/node, 4 cols each; fp16 output (logits only)
// ---------------------------------------------------------------------------
__global__ void k_gather2(const float* __restrict__ b2, int n) {
    int lane = threadIdx.x & 31;
    int t    = lane & 7;
    int node = blockIdx.x * 32 + (threadIdx.x >> 3);
    if (node >= n) return;
    unsigned gmask = 0xFFu << (lane & 24);
    int beg = g_off[node];
    int end = beg + g_cnt[node];
    const uint2* rows = reinterpret_cast<const uint2*>(g_h2h);  // 8 uint2 / row
    float acc[4];
    #pragma unroll
    for (int k = 0; k < 4; k++) acc[k] = 0.0f;
    int nfull = (end - beg) & ~7;
    int i = beg;
    for (; i < beg + nfull; i += 8) {
        float2 e = g_csr[i + t];
        #pragma unroll
        for (int k = 0; k < 8; k++) {
            float ex = __shfl_sync(gmask, e.x, k, 8);
            float ey = __shfl_sync(gmask, e.y, k, 8);
            uint2 r = rows[__float_as_int(ex) * 8 + t];
            add_row4(acc, r, ey);
        }
    }
    if (i < end) {
        float2 e = (i + t < end) ? g_csr[i + t] : make_float2(0.f, 0.f);
        int rem = end - i;
        #pragma unroll
        for (int k = 0; k < 8; k++) {
            if (k >= rem) break;
            float ex = __shfl_sync(gmask, e.x, k, 8);
            float ey = __shfl_sync(gmask, e.y, k, 8);
            uint2 r = rows[__float_as_int(ex) * 8 + t];
            add_row4(acc, r, ey);
        }
    }
    float di = g_dinv[node];
    float d2 = di * di;
    float4 s4 = *reinterpret_cast<const float4*>(g_h2 + node * D_OUT + t * 4);
    float4 b4 = *reinterpret_cast<const float4*>(b2 + t * 4);
    float o0 = fmaf(s4.x, d2, acc[0]) + b4.x;
    float o1 = fmaf(s4.y, d2, acc[1]) + b4.y;
    float o2 = fmaf(s4.z, d2, acc[2]) + b4.z;
    float o3 = fmaf(s4.w, d2, acc[3]) + b4.w;
    __half2 h0 = __floats2half2_rn(o0, o1);
    __half2 h1 = __floats2half2_rn(o2, o3);
    uint2 packed;
    packed.x = *reinterpret_cast<unsigned*>(&h0);
    packed.y = *reinterpret_cast<unsigned*>(&h1);
    reinterpret_cast<uint2*>(g_a2h)[node * 8 + t] = packed;
}

// ---------------------------------------------------------------------------
// 8) per-edge logits: ONE thread per edge, full fp16 rows (4x uint4 each),
//    MLP=8 independent loads, fp32 accumulate, no shuffles
// ---------------------------------------------------------------------------
__global__ void k_logits(float* __restrict__ out, int E) {
    int e = blockIdx.x * blockDim.x + threadIdx.x;
    if (e >= E) return;
    int s = g_src[e];
    int d = g_dst[e];
    const uint4* rows = reinterpret_cast<const uint4*>(g_a2h);  // 4 uint4 / row
    uint4 rs[4], rd[4];
    #pragma unroll
    for (int k = 0; k < 4; k++) rs[k] = rows[s * 4 + k];
    #pragma unroll
    for (int k = 0; k < 4; k++) rd[k] = rows[d * 4 + k];
    float p = 0.0f;
    #pragma unroll
    for (int k = 0; k < 4; k++) {
        __half2* hs = reinterpret_cast<__half2*>(&rs[k]);
        __half2* hd = reinterpret_cast<__half2*>(&rd[k]);
        #pragma unroll
        for (int j = 0; j < 4; j++) {
            float2 fs = __half22float2(hs[j]);
            float2 fd = __half22float2(hd[j]);
            p = fmaf(fs.x, fd.x, p);
            p = fmaf(fs.y, fd.y, p);
        }
    }
    out[e] = p;
}

// ---------------------------------------------------------------------------
extern "C" void kernel_launch(void* const* d_in, const int* in_sizes, int n_in,
                              void* d_out, int out_size) {
    const float* x   = (const float*)d_in[0];
    const void*  ei  = d_in[1];
    const float* W1  = (const float*)d_in[2];
    const float* b1  = (const float*)d_in[3];
    const float* W2  = (const float*)d_in[4];
    const float* b2  = (const float*)d_in[5];
    float*       out = (float*)d_out;

    int N = in_sizes[0] / D_IN; if (N > N_NODES) N = N_NODES;
    int E = in_sizes[1] / 2;    if (E > MAX_E)   E = MAX_E;
    const int T = 256;
    const int scan_blocks = (NW * 32 + T - 1) / T;

    k_init<<<(N + T - 1) / T, T>>>(ei, N);
    k_convert<<<(2 * E + T - 1) / T, T>>>(ei, E);

    k_scan_a<<<scan_blocks, T>>>(N);
    k_scan_b<<<1, 256>>>();
    k_scan_c<<<scan_blocks, T>>>(N);
    k_csr_fill<<<(E + T - 1) / T, T>>>(E);

    k_gemm1<<<(N + 3) / 4, T>>>(x, W1, N);
    k_gather1<<<(N + 31) / 32, T>>>(b1, N);

    k_gemm2<<<(N + 7) / 8, T>>>(W2, N);
    k_gather2<<<(N + 31) / 32, T>>>(b2, N);

    k_logits<<<(E + T - 1) / T, T>>>(out, E);
}